// round 15
// baseline (speedup 1.0000x reference)
#include <cuda_runtime.h>
#include <cuda_bf16.h>
#include <cstdint>

#define BB 4
#define CC 16
#define KK 16
#define HWHW (512 * 512)          // 262144
#define WPX 64                    // pixels per warp-iteration window
#define NW (HWHW / WPX)           // 4096 windows per batch
#define GRIDX 111                 // 111*4 = 444 blocks = 3/SM, single wave
#define NTH 128
#define NSTREAM (2 * GRIDX)       // 222 window-streams per batch

// stats per (b,k): [0..15] channel sums, [16] sum ||e||^2 over fg, [17] count
__device__ float g_stats[BB][KK][18];   // zeroed at load; re-zeroed by last block each launch
__device__ unsigned int g_done;

// ---------------- f32x2 helpers ----------------
__device__ __forceinline__ void fma2(unsigned long long& acc, unsigned long long a, unsigned long long b) {
    asm("fma.rn.f32x2 %0, %1, %2, %3;" : "=l"(acc) : "l"(a), "l"(b), "l"(acc));
}
__device__ __forceinline__ void add2(unsigned long long& acc, unsigned long long a) {
    asm("add.rn.f32x2 %0, %1, %2;" : "=l"(acc) : "l"(acc), "l"(a));
}
__device__ __forceinline__ float unpack_sum(unsigned long long v) {
    float lo, hi;
    asm("mov.b64 {%0, %1}, %2;" : "=f"(lo), "=f"(hi) : "l"(v));
    return lo + hi;
}
// mask bits {0,1} -> packed f32x2 {m0*1.0f, m1*1.0f}: exact, integer-pipe only
__device__ __forceinline__ unsigned long long mpack(unsigned a, unsigned b) {
    unsigned long long r;
    asm("mov.b64 %0, {%1, %2};" : "=l"(r) : "r"(a * 0x3F800000u), "r"(b * 0x3F800000u));
    return r;
}
__device__ __forceinline__ float warp_sum(float x) {
#pragma unroll
    for (int off = 16; off > 0; off >>= 1)
        x += __shfl_down_sync(0xffffffffu, x, off);
    return x;
}
// reduce a packed f32x2 within a 16-lane half, return lo+hi
__device__ __forceinline__ float half_sum_pk(unsigned long long v) {
#pragma unroll
    for (int off = 8; off > 0; off >>= 1) {
        unsigned long long o = __shfl_down_sync(0xffffffffu, v, off, 16);
        add2(v, o);
    }
    return unpack_sum(v);
}

// ---------------- fused kernel: batched LDG.128, no smem staging, no barriers ----------------
__global__ __launch_bounds__(NTH, 3)
void stats_kernel(const float* __restrict__ emb, const int* __restrict__ mask,
                  float* __restrict__ out) {
    const int b   = blockIdx.y;
    const int bx  = blockIdx.x;
    const int tid = threadIdx.x;
    const int w   = tid >> 5;
    const int l   = tid & 31;
    const int h   = l >> 4;          // half-warp -> channel group c0 = 8h
    const int hl  = l & 15;          // lane within half -> owns pixel quad hl of the window
    const int kg  = w & 1;           // k-group: k = 8*kg + kk
    const int pairid = w >> 1;       // window-stream id within block (team w, w+2 share emb)
    const int c0  = h * 8;
    const int k0  = kg * 8;

    const float* embB = emb  + (size_t)b * CC * HWHW;
    const int*   mskB = mask + (size_t)b * KK * HWHW;

    unsigned long long acc2[8][8];   // [kk][c-local], f32x2 over pixel pairs
    unsigned long long ssq2[8];
    int icnt[8];
#pragma unroll
    for (int kk = 0; kk < 8; ++kk) {
#pragma unroll
        for (int c = 0; c < 8; ++c) acc2[kk][c] = 0ull;
        ssq2[kk] = 0ull; icnt[kk] = 0;
    }

    for (int ch = bx * 2 + pairid; ch < NW; ch += NSTREAM) {
        const int p0 = ch * WPX + hl * 4;   // this lane's 4 pixels

        // ---- batched loads: all 16 LDG.128 issued before any consumption ----
        uint4 mr[8];
#pragma unroll
        for (int kk = 0; kk < 8; ++kk)
            mr[kk] = *(const uint4*)(mskB + (size_t)(k0 + kk) * HWHW + p0);

        unsigned long long fA[8], fB[8];
#pragma unroll
        for (int kk = 0; kk < 8; ++kk) {
            fA[kk] = mpack(mr[kk].x, mr[kk].y);
            fB[kk] = mpack(mr[kk].z, mr[kk].w);
            icnt[kk] += (int)(mr[kk].x + mr[kk].y + mr[kk].z + mr[kk].w);
        }

        unsigned long long s2x = 0ull, s2y = 0ull;
#pragma unroll
        for (int g = 0; g < 2; ++g) {
            ulonglong2 er[4];
#pragma unroll
            for (int c = 0; c < 4; ++c)
                er[c] = *(const ulonglong2*)(embB + (size_t)(c0 + g * 4 + c) * HWHW + p0);
#pragma unroll
            for (int c = 0; c < 4; ++c) {
                fma2(s2x, er[c].x, er[c].x);
                fma2(s2y, er[c].y, er[c].y);
#pragma unroll
                for (int kk = 0; kk < 8; ++kk) {
                    fma2(acc2[kk][g * 4 + c], er[c].x, fA[kk]);
                    fma2(acc2[kk][g * 4 + c], er[c].y, fB[kk]);
                }
            }
        }
#pragma unroll
        for (int kk = 0; kk < 8; ++kk) {
            fma2(ssq2[kk], s2x, fA[kk]);
            fma2(ssq2[kk], s2y, fB[kk]);
        }
    }

    // ---- reductions + global accumulate ----
#pragma unroll
    for (int kk = 0; kk < 8; ++kk) {
        const int k = k0 + kk;
        // channel sums: channels are half-local -> reduce within 16-lane half
#pragma unroll
        for (int c = 0; c < 8; ++c) {
            float v = half_sum_pk(acc2[kk][c]);
            if (hl == 0) atomicAdd(&g_stats[b][k][c0 + c], v);
        }
        // ssq: halves cover disjoint channels -> full-warp sum
        float s = warp_sum(unpack_sum(ssq2[kk]));
        // cnt: both halves counted every pixel -> halve
        float n = warp_sum((float)icnt[kk]) * 0.5f;
        if (l == 0) {
            atomicAdd(&g_stats[b][k][16], s);
            atomicAdd(&g_stats[b][k][17], n);
        }
    }

    // ---- last-block epilogue: compute loss, write out, reset globals ----
    __shared__ float sh_means[BB][KK][CC];
    __shared__ float sh_pull[BB][KK];
    __shared__ float sh_valid[BB][KK];
    __shared__ float sh_push[BB];
    __shared__ float sh_pullb[BB];
    __shared__ float sh_M[BB];
    __shared__ bool is_last;

    __threadfence();
    __syncthreads();
    if (tid == 0) {
        unsigned int v = atomicAdd(&g_done, 1u);
        is_last = (v == (unsigned int)(BB * GRIDX) - 1u);
    }
    __syncthreads();
    if (!is_last) return;
    __threadfence();

    const int t = tid;
    if (t < BB) sh_push[t] = 0.0f;

    if (t < BB * KK) {
        int bb = t >> 4, k = t & 15;
        volatile float* s = g_stats[bb][k];
        float cntv = s[17];
        float ssqv = s[16];
        bool valid = cntv > 0.0f;
        float inv = 1.0f / fmaxf(cntv, 1.0f);
        float dot = 0.0f;
#pragma unroll
        for (int c = 0; c < CC; ++c) {
            float sv = s[c];
            float m = sv * inv;
            sh_means[bb][k][c] = m;
            dot = fmaf(sv, m, dot);
        }
        sh_pull[bb][k]  = valid ? (ssqv - dot) / (cntv + 1e-6f) : 0.0f;
        sh_valid[bb][k] = valid ? 1.0f : 0.0f;
    }
    __syncthreads();

    for (int q = t; q < BB * KK * 18; q += NTH)
        ((float*)g_stats)[q] = 0.0f;
    if (t == 0) g_done = 0u;

    if (t < BB) {
        float M = 0.0f, ps = 0.0f;
        for (int k = 0; k < KK; ++k) { M += sh_valid[t][k]; ps += sh_pull[t][k]; }
        sh_M[t]     = M;
        sh_pullb[t] = ps / fmaxf(M, 1.0f);
    }

    float local[BB] = {0.0f, 0.0f, 0.0f, 0.0f};
    for (int idx = t; idx < BB * KK * KK; idx += NTH) {
        int bb = idx >> 8;
        int ij = idx & 255;
        int ii = ij >> 4, jj = ij & 15;
        if (ii < jj && sh_valid[bb][ii] > 0.0f && sh_valid[bb][jj] > 0.0f) {
            float d2 = 0.0f;
#pragma unroll
            for (int c = 0; c < CC; ++c) {
                float d = sh_means[bb][ii][c] - sh_means[bb][jj][c];
                d2 = fmaf(d, d, d2);
            }
            float dist = sqrtf(d2 + 1e-12f);
            float tm = fmaxf(1.5f - dist, 0.0f);
            local[bb] += tm * tm;
        }
    }
#pragma unroll
    for (int bb = 0; bb < BB; ++bb)
        if (local[bb] != 0.0f) atomicAdd(&sh_push[bb], local[bb]);
    __syncthreads();

    if (t == 0) {
        float loss = 0.0f;
        for (int bb = 0; bb < BB; ++bb) {
            float M = sh_M[bb];
            float npairs = M * (M - 1.0f) * 0.5f;
            float push = (M > 1.0f) ? sh_push[bb] / fmaxf(npairs, 1.0f) : 0.0f;
            loss += 0.5f * sh_pullb[bb] + push;   // DELTA_PULL = 0.5
        }
        out[0] = loss * (1.0f / BB);
    }
}

extern "C" void kernel_launch(void* const* d_in, const int* in_sizes, int n_in,
                              void* d_out, int out_size) {
    const float* emb  = (const float*)d_in[0];
    const int*   mask = (const int*)d_in[1];
    float* out = (float*)d_out;

    dim3 grid(GRIDX, BB);
    stats_kernel<<<grid, NTH>>>(emb, mask, out);
}

// round 16
// speedup vs baseline: 2.2845x; 2.2845x over previous
#include <cuda_runtime.h>
#include <cuda_bf16.h>
#include <cstdint>

#define BB 4
#define CC 16
#define KK 16
#define HWHW (512 * 512)          // 262144
#define CHUNK 64                  // pixels per stage
#define NCHUNK (HWHW / CHUNK)     // 4096
#define GRIDX 148                 // 148*4 = 592 blocks = 4/SM, single wave
#define NTH 128
#define KPW 4                     // k's per warp (4 warps x 4 = 16)
#define NSTAGE 6

#define EMB_STAGE_FLOATS (CC * CHUNK)       // 1024 floats = 4 KB
#define MSK_STAGE_INTS   (KK * CHUNK)       // 1024 ints   = 4 KB
#define STAGE_BYTES (EMB_STAGE_FLOATS * 4 + MSK_STAGE_INTS * 4)   // 8 KB
#define SMEM_BYTES (NSTAGE * STAGE_BYTES)   // 48 KB -> 4 blocks/SM

// stats per (b,k): [0..15] channel sums, [16] sum ||e||^2 over fg, [17] count
__device__ float g_stats[BB][KK][18];   // zeroed at load; re-zeroed by last block each launch
__device__ unsigned int g_done;

__device__ __forceinline__ float warp_sum(float x) {
#pragma unroll
    for (int off = 16; off > 0; off >>= 1)
        x += __shfl_down_sync(0xffffffffu, x, off);
    return x;
}
__device__ __forceinline__ void cp_async16(uint32_t dst_smem, const void* src) {
    asm volatile("cp.async.cg.shared.global [%0], [%1], 16;" :: "r"(dst_smem), "l"(src) : "memory");
}

// ---------------- fused kernel (R9 champion + CONTIGUOUS chunk ranges) ----------------
__global__ __launch_bounds__(NTH, 4)
void stats_kernel(const float* __restrict__ emb, const int* __restrict__ mask,
                  float* __restrict__ out) {
    extern __shared__ char smraw[];

    const int b   = blockIdx.y;
    const int bx  = blockIdx.x;
    const int tid = threadIdx.x;
    const int w   = tid >> 5;
    const int l   = tid & 31;

    // contiguous chunk range for this block -> every global stream is SEQUENTIAL
    const int ch_begin = (int)(((long long)bx * NCHUNK) / GRIDX);
    const int ch_end   = (int)(((long long)(bx + 1) * NCHUNK) / GRIDX);

    const float* embB = emb  + (size_t)b * CC * HWHW;
    const int*   mskB = mask + (size_t)b * KK * HWHW;

    float acc[KPW][CC];
    float ssq[KPW], cnt[KPW];
#pragma unroll
    for (int kk = 0; kk < KPW; ++kk) {
#pragma unroll
        for (int c = 0; c < CC; ++c) acc[kk][c] = 0.0f;
        ssq[kk] = 0.0f; cnt[kk] = 0.0f;
    }

    // per stage: 256 emb + 256 mask 16B units -> 4 cp.async per thread
    auto prefetch = [&](int stage, int ch) {
        if (ch < ch_end) {
            const int pix0 = ch * CHUNK;
            uint32_t se = (uint32_t)__cvta_generic_to_shared(smraw + stage * STAGE_BYTES);
            uint32_t sk = se + EMB_STAGE_FLOATS * 4;
#pragma unroll
            for (int j = 0; j < 2; ++j) {
                int u   = tid + j * NTH;        // 0..255
                int c   = u >> 4;               // channel (16 16B units per 64-float row)
                int off = (u & 15) << 2;        // float offset within row
                cp_async16(se + (uint32_t)(c * CHUNK + off) * 4,
                           embB + (size_t)c * HWHW + pix0 + off);
            }
#pragma unroll
            for (int j = 0; j < 2; ++j) {
                int u   = tid + j * NTH;
                int k   = u >> 4;
                int off = (u & 15) << 2;
                cp_async16(sk + (uint32_t)(k * CHUNK + off) * 4,
                           mskB + (size_t)k * HWHW + pix0 + off);
            }
        }
        asm volatile("cp.async.commit_group;" ::: "memory");
    };

    // fill NSTAGE-1 stages -> up to 5 sequential 256B-per-stream fetches in flight
#pragma unroll
    for (int s = 0; s < NSTAGE - 1; ++s)
        prefetch(s, ch_begin + s);

    int cons = 0, pf = NSTAGE - 1;
    for (int ch = ch_begin; ch < ch_end; ++ch) {
        asm volatile("cp.async.wait_group %0;" :: "n"(NSTAGE - 2) : "memory");
        __syncthreads();
        const float* eb = (const float*)(smraw + cons * STAGE_BYTES);
        const int*   mb = (const int*)(smraw + cons * STAGE_BYTES + EMB_STAGE_FLOATS * 4);

        // lane l owns pixels {2l, 2l+1}; masks are exactly 0/1 -> direct I2F
        float mf[KPW][2];
#pragma unroll
        for (int kk = 0; kk < KPW; ++kk) {
            int2 m = ((const int2*)(mb + (w * KPW + kk) * CHUNK))[l];
            mf[kk][0] = (float)m.x;
            mf[kk][1] = (float)m.y;
        }

        float s2a = 0.0f, s2b = 0.0f;
#pragma unroll
        for (int c = 0; c < CC; ++c) {
            float2 e = ((const float2*)(eb + c * CHUNK))[l];
            s2a = fmaf(e.x, e.x, s2a);
            s2b = fmaf(e.y, e.y, s2b);
#pragma unroll
            for (int kk = 0; kk < KPW; ++kk) {
                float a = acc[kk][c];
                a = fmaf(e.x, mf[kk][0], a);
                a = fmaf(e.y, mf[kk][1], a);
                acc[kk][c] = a;
            }
        }
#pragma unroll
        for (int kk = 0; kk < KPW; ++kk) {
            float s = ssq[kk];
            s = fmaf(s2a, mf[kk][0], s);
            s = fmaf(s2b, mf[kk][1], s);
            ssq[kk] = s;
            cnt[kk] += mf[kk][0] + mf[kk][1];
        }

        // prefetch targets the stage consumed LAST iteration; all warps passed
        // this iteration's top barrier after finishing that read -> safe
        prefetch(pf, ch + NSTAGE - 1);
        cons = (cons + 1 == NSTAGE) ? 0 : cons + 1;
        pf   = (pf   + 1 == NSTAGE) ? 0 : pf   + 1;
    }

    // ---- warp reduce + global accumulate ----
#pragma unroll
    for (int kk = 0; kk < KPW; ++kk) {
        const int k = w * KPW + kk;
#pragma unroll
        for (int c = 0; c < CC; ++c) {
            float v = warp_sum(acc[kk][c]);
            if (l == 0) atomicAdd(&g_stats[b][k][c], v);
        }
        float s = warp_sum(ssq[kk]);
        float n = warp_sum(cnt[kk]);
        if (l == 0) {
            atomicAdd(&g_stats[b][k][16], s);
            atomicAdd(&g_stats[b][k][17], n);
        }
    }

    // ---- last-block epilogue: compute loss, write out, reset globals ----
    __shared__ bool is_last;
    __threadfence();
    if (tid == 0) {
        unsigned int v = atomicAdd(&g_done, 1u);
        is_last = (v == (unsigned int)(BB * GRIDX) - 1u);
    }
    __syncthreads();
    if (!is_last) return;
    __threadfence();

    float* sh_means = (float*)smraw;                      // [BB][KK][CC] = 1024 floats
    float* sh_pull  = sh_means + BB * KK * CC;
    float* sh_valid = sh_pull + BB * KK;
    float* sh_push  = sh_valid + BB * KK;
    float* sh_pullb = sh_push + BB;
    float* sh_M     = sh_pullb + BB;

    const int t = tid;
    if (t < BB) sh_push[t] = 0.0f;

    if (t < BB * KK) {
        int bb = t >> 4, k = t & 15;
        volatile float* s = g_stats[bb][k];
        float cntv = s[17];
        float ssqv = s[16];
        bool valid = cntv > 0.0f;
        float inv = 1.0f / fmaxf(cntv, 1.0f);
        float dot = 0.0f;
#pragma unroll
        for (int c = 0; c < CC; ++c) {
            float sv = s[c];
            float m = sv * inv;
            sh_means[(bb * KK + k) * CC + c] = m;
            dot = fmaf(sv, m, dot);
        }
        sh_pull[bb * KK + k]  = valid ? (ssqv - dot) / (cntv + 1e-6f) : 0.0f;
        sh_valid[bb * KK + k] = valid ? 1.0f : 0.0f;
    }
    __syncthreads();

    for (int q = t; q < BB * KK * 18; q += NTH)
        ((float*)g_stats)[q] = 0.0f;
    if (t == 0) g_done = 0u;

    if (t < BB) {
        float M = 0.0f, ps = 0.0f;
        for (int k = 0; k < KK; ++k) { M += sh_valid[t * KK + k]; ps += sh_pull[t * KK + k]; }
        sh_M[t]     = M;
        sh_pullb[t] = ps / fmaxf(M, 1.0f);
    }

    float local[BB] = {0.0f, 0.0f, 0.0f, 0.0f};
    for (int idx = t; idx < BB * KK * KK; idx += NTH) {
        int bb = idx >> 8;
        int ij = idx & 255;
        int ii = ij >> 4, jj = ij & 15;
        if (ii < jj && sh_valid[bb * KK + ii] > 0.0f && sh_valid[bb * KK + jj] > 0.0f) {
            float d2 = 0.0f;
#pragma unroll
            for (int c = 0; c < CC; ++c) {
                float d = sh_means[(bb * KK + ii) * CC + c] - sh_means[(bb * KK + jj) * CC + c];
                d2 = fmaf(d, d, d2);
            }
            float dist = sqrtf(d2 + 1e-12f);
            float tm = fmaxf(1.5f - dist, 0.0f);
            local[bb] += tm * tm;
        }
    }
#pragma unroll
    for (int bb = 0; bb < BB; ++bb)
        if (local[bb] != 0.0f) atomicAdd(&sh_push[bb], local[bb]);
    __syncthreads();

    if (t == 0) {
        float loss = 0.0f;
        for (int bb = 0; bb < BB; ++bb) {
            float M = sh_M[bb];
            float npairs = M * (M - 1.0f) * 0.5f;
            float push = (M > 1.0f) ? sh_push[bb] / fmaxf(npairs, 1.0f) : 0.0f;
            loss += 0.5f * sh_pullb[bb] + push;   // DELTA_PULL = 0.5
        }
        out[0] = loss * (1.0f / BB);
    }
}

extern "C" void kernel_launch(void* const* d_in, const int* in_sizes, int n_in,
                              void* d_out, int out_size) {
    const float* emb  = (const float*)d_in[0];
    const int*   mask = (const int*)d_in[1];
    float* out = (float*)d_out;

    cudaFuncSetAttribute(stats_kernel, cudaFuncAttributeMaxDynamicSharedMemorySize, SMEM_BYTES);

    dim3 grid(GRIDX, BB);
    stats_kernel<<<grid, NTH, SMEM_BYTES>>>(emb, mask, out);
}